// round 3
// baseline (speedup 1.0000x reference)
#include <cuda_runtime.h>
#include <math_constants.h>

#define BATCH 4
#define SEQ   2048
#define DIM   1024

// Scratch (static device arrays: allocation-guard-safe)
__device__ float d_Q[BATCH * SEQ * DIM];
__device__ float d_K[BATCH * SEQ * DIM];
__device__ float d_V[BATCH * SEQ * DIM];
__device__ float d_S[(size_t)BATCH * SEQ * SEQ];   // scores -> probabilities in place

// ---------------------------------------------------------------------------
// GEMM NT: C[m,n] = sum_k A[m,k] * B[n,k]   (both K-contiguous, row-major)
// Tile 64x64, BK=16, 256 threads, 4x4 micro-tile.
// ---------------------------------------------------------------------------

// QKV projection: x[8192,1024] @ W[1024,1024]^T, blockIdx.z selects Wq/Wk/Wv.
__global__ __launch_bounds__(256) void qkv_kernel(const float* __restrict__ x,
                                                  const float* __restrict__ Wq,
                                                  const float* __restrict__ Wk,
                                                  const float* __restrict__ Wv) {
    const float* W;
    float* out;
    if (blockIdx.z == 0)      { W = Wq; out = d_Q; }
    else if (blockIdx.z == 1) { W = Wk; out = d_K; }
    else                      { W = Wv; out = d_V; }

    const int Kd = DIM, N = DIM;
    const int m0 = blockIdx.y * 64, n0 = blockIdx.x * 64;

    __shared__ float As[16][64];
    __shared__ float Bs[16][64];

    const int t  = threadIdx.y * 16 + threadIdx.x;
    const int lr = t >> 2;            // 0..63
    const int lk = (t & 3) << 2;      // 0,4,8,12

    float acc[4][4] = {};

    for (int k0 = 0; k0 < Kd; k0 += 16) {
        float4 a4 = *(const float4*)(x + (size_t)(m0 + lr) * Kd + k0 + lk);
        float4 b4 = *(const float4*)(W + (size_t)(n0 + lr) * Kd + k0 + lk);
        As[lk + 0][lr] = a4.x; As[lk + 1][lr] = a4.y; As[lk + 2][lr] = a4.z; As[lk + 3][lr] = a4.w;
        Bs[lk + 0][lr] = b4.x; Bs[lk + 1][lr] = b4.y; Bs[lk + 2][lr] = b4.z; Bs[lk + 3][lr] = b4.w;
        __syncthreads();
#pragma unroll
        for (int kk = 0; kk < 16; ++kk) {
            float4 av = *(const float4*)&As[kk][threadIdx.y * 4];
            float4 bv = *(const float4*)&Bs[kk][threadIdx.x * 4];
            float a[4] = {av.x, av.y, av.z, av.w};
            float b[4] = {bv.x, bv.y, bv.z, bv.w};
#pragma unroll
            for (int i = 0; i < 4; ++i)
#pragma unroll
                for (int j = 0; j < 4; ++j)
                    acc[i][j] += a[i] * b[j];
        }
        __syncthreads();
    }
#pragma unroll
    for (int i = 0; i < 4; ++i) {
        float4 v = make_float4(acc[i][0], acc[i][1], acc[i][2], acc[i][3]);
        *(float4*)(out + (size_t)(m0 + threadIdx.y * 4 + i) * N + n0 + threadIdx.x * 4) = v;
    }
}

// Scores: S[b] = Q[b] @ K[b]^T, [2048,2048], skip tiles strictly above diagonal.
__global__ __launch_bounds__(256) void scores_kernel() {
    if (blockIdx.x > blockIdx.y) return;   // fully-masked tile: never read later

    const int b = blockIdx.z;
    const float* A = d_Q + (size_t)b * SEQ * DIM;
    const float* B = d_K + (size_t)b * SEQ * DIM;
    float* C = d_S + (size_t)b * SEQ * SEQ;

    const int m0 = blockIdx.y * 64, n0 = blockIdx.x * 64;

    __shared__ float As[16][64];
    __shared__ float Bs[16][64];

    const int t  = threadIdx.y * 16 + threadIdx.x;
    const int lr = t >> 2;
    const int lk = (t & 3) << 2;

    float acc[4][4] = {};

    for (int k0 = 0; k0 < DIM; k0 += 16) {
        float4 a4 = *(const float4*)(A + (size_t)(m0 + lr) * DIM + k0 + lk);
        float4 b4 = *(const float4*)(B + (size_t)(n0 + lr) * DIM + k0 + lk);
        As[lk + 0][lr] = a4.x; As[lk + 1][lr] = a4.y; As[lk + 2][lr] = a4.z; As[lk + 3][lr] = a4.w;
        Bs[lk + 0][lr] = b4.x; Bs[lk + 1][lr] = b4.y; Bs[lk + 2][lr] = b4.z; Bs[lk + 3][lr] = b4.w;
        __syncthreads();
#pragma unroll
        for (int kk = 0; kk < 16; ++kk) {
            float4 av = *(const float4*)&As[kk][threadIdx.y * 4];
            float4 bv = *(const float4*)&Bs[kk][threadIdx.x * 4];
            float a[4] = {av.x, av.y, av.z, av.w};
            float b[4] = {bv.x, bv.y, bv.z, bv.w};
#pragma unroll
            for (int i = 0; i < 4; ++i)
#pragma unroll
                for (int j = 0; j < 4; ++j)
                    acc[i][j] += a[i] * b[j];
        }
        __syncthreads();
    }
#pragma unroll
    for (int i = 0; i < 4; ++i) {
        float4 v = make_float4(acc[i][0], acc[i][1], acc[i][2], acc[i][3]);
        *(float4*)(C + (size_t)(m0 + threadIdx.y * 4 + i) * SEQ + n0 + threadIdx.x * 4) = v;
    }
}

// Causal softmax over each row i: p[j] = softmax_{j<=i}(s[j] * 1/32), zeros for j>i.
__global__ __launch_bounds__(256) void softmax_kernel() {
    const int i = blockIdx.x;
    const int b = blockIdx.y;
    float* row = d_S + ((size_t)b * SEQ + i) * SEQ;
    const float scale = 0.03125f;   // 1/sqrt(1024)
    const int len = i + 1;
    const int t = threadIdx.x;

    __shared__ float red[256];

    float m = -CUDART_INF_F;
    for (int j = t; j < len; j += 256) m = fmaxf(m, row[j]);
    red[t] = m; __syncthreads();
    for (int s = 128; s > 0; s >>= 1) {
        if (t < s) red[t] = fmaxf(red[t], red[t + s]);
        __syncthreads();
    }
    m = red[0] * scale;
    __syncthreads();

    float sum = 0.f;
    for (int j = t; j < len; j += 256) {
        float e = __expf(row[j] * scale - m);
        row[j] = e;
        sum += e;
    }
    red[t] = sum; __syncthreads();
    for (int s = 128; s > 0; s >>= 1) {
        if (t < s) red[t] += red[t + s];
        __syncthreads();
    }
    const float inv = 1.f / red[0];

    for (int j = t; j < len; j += 256) row[j] *= inv;
    for (int j = len + t; j < SEQ; j += 256) row[j] = 0.f;   // zero pad for PV reads
}

// ---------------------------------------------------------------------------
// GEMM NN: O[b] = P[b] @ V[b], P [2048,2048], V [2048,1024].
// Causal: k-loop runs only to the end of this query tile's diagonal.
// ---------------------------------------------------------------------------
__global__ __launch_bounds__(256) void pv_kernel(float* __restrict__ out) {
    const int b = blockIdx.z;
    const float* A = d_S + (size_t)b * SEQ * SEQ;
    const float* B = d_V + (size_t)b * SEQ * DIM;
    float* C = out + (size_t)b * SEQ * DIM;

    const int m0 = blockIdx.y * 64, n0 = blockIdx.x * 64;
    const int kEnd = m0 + 64;   // P[m, k>m] == 0, tile-aligned

    __shared__ float As[16][64];
    __shared__ float Bs[16][64];

    const int t  = threadIdx.y * 16 + threadIdx.x;
    const int lr = t >> 2;            // A-load row
    const int lk = (t & 3) << 2;      // A-load k
    const int bk = t >> 4;            // B-load k row
    const int bn = (t & 15) << 2;     // B-load n

    float acc[4][4] = {};

    for (int k0 = 0; k0 < kEnd; k0 += 16) {
        float4 a4 = *(const float4*)(A + (size_t)(m0 + lr) * SEQ + k0 + lk);
        As[lk + 0][lr] = a4.x; As[lk + 1][lr] = a4.y; As[lk + 2][lr] = a4.z; As[lk + 3][lr] = a4.w;
        float4 b4 = *(const float4*)(B + (size_t)(k0 + bk) * DIM + n0 + bn);
        *(float4*)&Bs[bk][bn] = b4;
        __syncthreads();
#pragma unroll
        for (int kk = 0; kk < 16; ++kk) {
            float4 av = *(const float4*)&As[kk][threadIdx.y * 4];
            float4 bv = *(const float4*)&Bs[kk][threadIdx.x * 4];
            float a[4] = {av.x, av.y, av.z, av.w};
            float bb[4] = {bv.x, bv.y, bv.z, bv.w};
#pragma unroll
            for (int i = 0; i < 4; ++i)
#pragma unroll
                for (int j = 0; j < 4; ++j)
                    acc[i][j] += a[i] * bb[j];
        }
        __syncthreads();
    }
#pragma unroll
    for (int i = 0; i < 4; ++i) {
        float4 v = make_float4(acc[i][0], acc[i][1], acc[i][2], acc[i][3]);
        *(float4*)(C + (size_t)(m0 + threadIdx.y * 4 + i) * DIM + n0 + threadIdx.x * 4) = v;
    }
}

extern "C" void kernel_launch(void* const* d_in, const int* in_sizes, int n_in,
                              void* d_out, int out_size) {
    const float* x  = (const float*)d_in[0];
    const float* Wq = (const float*)d_in[1];
    const float* Wk = (const float*)d_in[2];
    const float* Wv = (const float*)d_in[3];
    float* out = (float*)d_out;

    dim3 thr(16, 16);

    // 1) Q,K,V projections: M=8192, N=1024, z selects weight
    qkv_kernel<<<dim3(DIM / 64, (BATCH * SEQ) / 64, 3), thr>>>(x, Wq, Wk, Wv);

    // 2) Scores = Q K^T per batch (lower-triangular tiles only)
    scores_kernel<<<dim3(SEQ / 64, SEQ / 64, BATCH), thr>>>();

    // 3) Causal softmax (scale 1/32 applied inside)
    softmax_kernel<<<dim3(SEQ, BATCH), 256>>>();

    // 4) O = P V per batch (k-loop truncated at diagonal)
    pv_kernel<<<dim3(DIM / 64, SEQ / 64, BATCH), thr>>>(out);
}

// round 4
// speedup vs baseline: 3.6420x; 3.6420x over previous
#include <cuda_runtime.h>
#include <math_constants.h>

#define BATCH 4
#define SEQ   2048
#define DIM   1024

// Scratch (static device arrays: allocation-guard-safe)
__device__ float d_Q[BATCH * SEQ * DIM];
__device__ float d_K[BATCH * SEQ * DIM];
__device__ float d_V[BATCH * SEQ * DIM];
__device__ float d_S[(size_t)BATCH * SEQ * SEQ];   // scores -> probabilities in place

// ---------------------------------------------------------------------------
// TF32 tensor-core GEMM building blocks
// Block tile 128x128, BK=16, 256 threads = 8 warps (2x4), warp tile 64x32.
// mma.sync.aligned.m16n8k8.row.col.f32.tf32.tf32.f32
// ---------------------------------------------------------------------------

#define SA_STRIDE 20     // 16 + 4 pad: fragment loads bank-conflict-free
#define SBNN_STRIDE 136  // 128 + 8 pad for [k][n] layout (PV)

__device__ __forceinline__ unsigned f2tf(float x) {
    unsigned u;
    asm("cvt.rna.tf32.f32 %0, %1;" : "=r"(u) : "f"(x));
    return u;
}

__device__ __forceinline__ void mma_tf32(float* d, const unsigned* a, const unsigned* b) {
    asm volatile(
        "mma.sync.aligned.m16n8k8.row.col.f32.tf32.tf32.f32 "
        "{%0,%1,%2,%3}, {%4,%5,%6,%7}, {%8,%9}, {%0,%1,%2,%3};\n"
        : "+f"(d[0]), "+f"(d[1]), "+f"(d[2]), "+f"(d[3])
        : "r"(a[0]), "r"(a[1]), "r"(a[2]), "r"(a[3]), "r"(b[0]), "r"(b[1]));
}

__device__ __forceinline__ void cp16(void* smem, const void* gmem) {
    unsigned s = (unsigned)__cvta_generic_to_shared(smem);
    asm volatile("cp.async.cg.shared.global [%0], [%1], 16;\n" :: "r"(s), "l"(gmem));
}
__device__ __forceinline__ void cp_commit() { asm volatile("cp.async.commit_group;\n"); }
__device__ __forceinline__ void cp_wait1() { asm volatile("cp.async.wait_group 1;\n"); }
__device__ __forceinline__ void cp_wait0() { asm volatile("cp.async.wait_group 0;\n"); }

// Load one 128x16 K-contiguous tile (A or NT-B) into smem [128][SA_STRIDE].
__device__ __forceinline__ void load_tile_kmajor(float* s, const float* g, int ld, int t) {
    const int row = t >> 2;            // 0..63
    const int c4  = (t & 3) << 2;      // 0,4,8,12
    cp16(&s[row * SA_STRIDE + c4],        g + (size_t)row * ld + c4);
    cp16(&s[(row + 64) * SA_STRIDE + c4], g + (size_t)(row + 64) * ld + c4);
}

// Load one 16x128 [k][n] tile (PV's V) into smem [16][SBNN_STRIDE].
__device__ __forceinline__ void load_tile_nmajor(float* s, const float* g, int ld, int t) {
    const int kr = t >> 5;             // 0..7
    const int c4 = (t & 31) << 2;      // 0..124
    cp16(&s[kr * SBNN_STRIDE + c4],       g + (size_t)kr * ld + c4);
    cp16(&s[(kr + 8) * SBNN_STRIDE + c4], g + (size_t)(kr + 8) * ld + c4);
}

// One BK=16 compute step, NT layout (both sA,sB are [128][SA_STRIDE], K-contiguous).
__device__ __forceinline__ void mma_step_NT(const float* sA, const float* sB,
                                            int m_off, int n_off, int g, int c,
                                            float acc[4][4][4]) {
#pragma unroll
    for (int kb = 0; kb < 16; kb += 8) {
        unsigned a[4][4], b[4][2];
#pragma unroll
        for (int im = 0; im < 4; ++im) {
            const int r = m_off + im * 16 + g;
            a[im][0] = f2tf(sA[r * SA_STRIDE + kb + c]);
            a[im][1] = f2tf(sA[(r + 8) * SA_STRIDE + kb + c]);
            a[im][2] = f2tf(sA[r * SA_STRIDE + kb + c + 4]);
            a[im][3] = f2tf(sA[(r + 8) * SA_STRIDE + kb + c + 4]);
        }
#pragma unroll
        for (int jn = 0; jn < 4; ++jn) {
            const int nn = n_off + jn * 8 + g;
            b[jn][0] = f2tf(sB[nn * SA_STRIDE + kb + c]);
            b[jn][1] = f2tf(sB[nn * SA_STRIDE + kb + c + 4]);
        }
#pragma unroll
        for (int im = 0; im < 4; ++im)
#pragma unroll
            for (int jn = 0; jn < 4; ++jn)
                mma_tf32(acc[im][jn], a[im], b[jn]);
    }
}

// One BK=16 compute step, NN layout (sB is [16][SBNN_STRIDE], n-contiguous).
__device__ __forceinline__ void mma_step_NN(const float* sA, const float* sB,
                                            int m_off, int n_off, int g, int c,
                                            float acc[4][4][4]) {
#pragma unroll
    for (int kb = 0; kb < 16; kb += 8) {
        unsigned a[4][4], b[4][2];
#pragma unroll
        for (int im = 0; im < 4; ++im) {
            const int r = m_off + im * 16 + g;
            a[im][0] = f2tf(sA[r * SA_STRIDE + kb + c]);
            a[im][1] = f2tf(sA[(r + 8) * SA_STRIDE + kb + c]);
            a[im][2] = f2tf(sA[r * SA_STRIDE + kb + c + 4]);
            a[im][3] = f2tf(sA[(r + 8) * SA_STRIDE + kb + c + 4]);
        }
#pragma unroll
        for (int jn = 0; jn < 4; ++jn) {
            const int nn = n_off + jn * 8 + g;
            b[jn][0] = f2tf(sB[(kb + c) * SBNN_STRIDE + nn]);
            b[jn][1] = f2tf(sB[(kb + c + 4) * SBNN_STRIDE + nn]);
        }
#pragma unroll
        for (int im = 0; im < 4; ++im)
#pragma unroll
            for (int jn = 0; jn < 4; ++jn)
                mma_tf32(acc[im][jn], a[im], b[jn]);
    }
}

__device__ __forceinline__ void store_acc(float* C, int ldc, int m0, int n0,
                                          int m_off, int n_off, int g, int c,
                                          float acc[4][4][4]) {
#pragma unroll
    for (int im = 0; im < 4; ++im) {
#pragma unroll
        for (int jn = 0; jn < 4; ++jn) {
            const int row = m0 + m_off + im * 16 + g;
            const int col = n0 + n_off + jn * 8 + 2 * c;
            float2 v0 = make_float2(acc[im][jn][0], acc[im][jn][1]);
            float2 v1 = make_float2(acc[im][jn][2], acc[im][jn][3]);
            *(float2*)(C + (size_t)row * ldc + col)       = v0;
            *(float2*)(C + (size_t)(row + 8) * ldc + col) = v1;
        }
    }
}

// ---------------------------------------------------------------------------
// 1) QKV projection: x[8192,1024] @ W[1024,1024]^T  (NT, z selects Wq/Wk/Wv)
// ---------------------------------------------------------------------------
__global__ __launch_bounds__(256, 2) void qkv_kernel(const float* __restrict__ x,
                                                     const float* __restrict__ Wq,
                                                     const float* __restrict__ Wk,
                                                     const float* __restrict__ Wv) {
    __shared__ float sA[2][128 * SA_STRIDE];
    __shared__ float sB[2][128 * SA_STRIDE];

    const float* W;
    float* out;
    if (blockIdx.z == 0)      { W = Wq; out = d_Q; }
    else if (blockIdx.z == 1) { W = Wk; out = d_K; }
    else                      { W = Wv; out = d_V; }

    const int m0 = blockIdx.y * 128, n0 = blockIdx.x * 128;
    const int t = threadIdx.x;
    const int wid = t >> 5, lane = t & 31, g = lane >> 2, c = lane & 3;
    const int m_off = (wid >> 2) * 64, n_off = (wid & 3) * 32;

    const float* gA = x + (size_t)m0 * DIM;
    const float* gB = W + (size_t)n0 * DIM;

    float acc[4][4][4] = {};
    const int nIter = DIM / 16;

    load_tile_kmajor(sA[0], gA, DIM, t);
    load_tile_kmajor(sB[0], gB, DIM, t);
    cp_commit();

    for (int it = 0; it < nIter; ++it) {
        if (it + 1 < nIter) {
            const int nb = (it + 1) & 1;
            load_tile_kmajor(sA[nb], gA + (it + 1) * 16, DIM, t);
            load_tile_kmajor(sB[nb], gB + (it + 1) * 16, DIM, t);
            cp_commit();
            cp_wait1();
        } else {
            cp_wait0();
        }
        __syncthreads();
        const int s = it & 1;
        mma_step_NT(sA[s], sB[s], m_off, n_off, g, c, acc);
        __syncthreads();
    }
    store_acc(out, DIM, m0, n0, m_off, n_off, g, c, acc);
}

// ---------------------------------------------------------------------------
// 2) Scores: S[b] = Q[b] @ K[b]^T  (NT, lower-triangular tiles only)
// ---------------------------------------------------------------------------
__global__ __launch_bounds__(256, 2) void scores_kernel() {
    if (blockIdx.x > blockIdx.y) return;  // fully-masked tile: never read later

    __shared__ float sA[2][128 * SA_STRIDE];
    __shared__ float sB[2][128 * SA_STRIDE];

    const int b = blockIdx.z;
    const int m0 = blockIdx.y * 128, n0 = blockIdx.x * 128;
    const int t = threadIdx.x;
    const int wid = t >> 5, lane = t & 31, g = lane >> 2, c = lane & 3;
    const int m_off = (wid >> 2) * 64, n_off = (wid & 3) * 32;

    const float* gA = d_Q + (size_t)b * SEQ * DIM + (size_t)m0 * DIM;
    const float* gB = d_K + (size_t)b * SEQ * DIM + (size_t)n0 * DIM;
    float* C = d_S + (size_t)b * SEQ * SEQ;

    float acc[4][4][4] = {};
    const int nIter = DIM / 16;

    load_tile_kmajor(sA[0], gA, DIM, t);
    load_tile_kmajor(sB[0], gB, DIM, t);
    cp_commit();

    for (int it = 0; it < nIter; ++it) {
        if (it + 1 < nIter) {
            const int nb = (it + 1) & 1;
            load_tile_kmajor(sA[nb], gA + (it + 1) * 16, DIM, t);
            load_tile_kmajor(sB[nb], gB + (it + 1) * 16, DIM, t);
            cp_commit();
            cp_wait1();
        } else {
            cp_wait0();
        }
        __syncthreads();
        const int s = it & 1;
        mma_step_NT(sA[s], sB[s], m_off, n_off, g, c, acc);
        __syncthreads();
    }
    store_acc(C, SEQ, m0, n0, m_off, n_off, g, c, acc);
}

// ---------------------------------------------------------------------------
// 3) Causal softmax (unchanged; scale 1/32 applied inside)
// ---------------------------------------------------------------------------
__global__ __launch_bounds__(256) void softmax_kernel() {
    const int i = blockIdx.x;
    const int b = blockIdx.y;
    float* row = d_S + ((size_t)b * SEQ + i) * SEQ;
    const float scale = 0.03125f;   // 1/sqrt(1024)
    const int len = i + 1;
    const int t = threadIdx.x;

    __shared__ float red[256];

    float m = -CUDART_INF_F;
    for (int j = t; j < len; j += 256) m = fmaxf(m, row[j]);
    red[t] = m; __syncthreads();
    for (int s = 128; s > 0; s >>= 1) {
        if (t < s) red[t] = fmaxf(red[t], red[t + s]);
        __syncthreads();
    }
    m = red[0] * scale;
    __syncthreads();

    float sum = 0.f;
    for (int j = t; j < len; j += 256) {
        float e = __expf(row[j] * scale - m);
        row[j] = e;
        sum += e;
    }
    red[t] = sum; __syncthreads();
    for (int s = 128; s > 0; s >>= 1) {
        if (t < s) red[t] += red[t + s];
        __syncthreads();
    }
    const float inv = 1.f / red[0];

    for (int j = t; j < len; j += 256) row[j] *= inv;
    for (int j = len + t; j < SEQ; j += 256) row[j] = 0.f;   // zero pad for PV reads
}

// ---------------------------------------------------------------------------
// 4) O = P @ V  (NN, k-loop truncated at the query tile's diagonal)
// ---------------------------------------------------------------------------
__global__ __launch_bounds__(256, 2) void pv_kernel(float* __restrict__ out) {
    __shared__ float sA[2][128 * SA_STRIDE];
    __shared__ float sB[2][16 * SBNN_STRIDE];

    const int b = blockIdx.z;
    const int m0 = blockIdx.y * 128, n0 = blockIdx.x * 128;
    const int t = threadIdx.x;
    const int wid = t >> 5, lane = t & 31, g = lane >> 2, c = lane & 3;
    const int m_off = (wid >> 2) * 64, n_off = (wid & 3) * 32;

    const float* gA = d_S + (size_t)b * SEQ * SEQ + (size_t)m0 * SEQ;
    const float* gB = d_V + (size_t)b * SEQ * DIM + n0;
    float* C = out + (size_t)b * SEQ * DIM;

    float acc[4][4][4] = {};
    const int nIter = (m0 + 128) / 16;   // P[m, k>m] == 0, tile-aligned

    load_tile_kmajor(sA[0], gA, SEQ, t);
    load_tile_nmajor(sB[0], gB, DIM, t);
    cp_commit();

    for (int it = 0; it < nIter; ++it) {
        if (it + 1 < nIter) {
            const int nb = (it + 1) & 1;
            load_tile_kmajor(sA[nb], gA + (it + 1) * 16, SEQ, t);
            load_tile_nmajor(sB[nb], gB + (size_t)(it + 1) * 16 * DIM, DIM, t);
            cp_commit();
            cp_wait1();
        } else {
            cp_wait0();
        }
        __syncthreads();
        const int s = it & 1;
        mma_step_NN(sA[s], sB[s], m_off, n_off, g, c, acc);
        __syncthreads();
    }
    store_acc(C, DIM, m0, n0, m_off, n_off, g, c, acc);
}

extern "C" void kernel_launch(void* const* d_in, const int* in_sizes, int n_in,
                              void* d_out, int out_size) {
    const float* x  = (const float*)d_in[0];
    const float* Wq = (const float*)d_in[1];
    const float* Wk = (const float*)d_in[2];
    const float* Wv = (const float*)d_in[3];
    float* out = (float*)d_out;

    // 1) Q,K,V projections: M=8192, N=1024, z selects weight
    qkv_kernel<<<dim3(DIM / 128, (BATCH * SEQ) / 128, 3), 256>>>(x, Wq, Wk, Wv);

    // 2) Scores = Q K^T per batch (lower-triangular tiles only)
    scores_kernel<<<dim3(SEQ / 128, SEQ / 128, BATCH), 256>>>();

    // 3) Causal softmax
    softmax_kernel<<<dim3(SEQ, BATCH), 256>>>();

    // 4) O = P V per batch (k-loop truncated at diagonal)
    pv_kernel<<<dim3(DIM / 128, SEQ / 128, BATCH), 256>>>(out);
}